// round 13
// baseline (speedup 1.0000x reference)
#include <cuda_runtime.h>
#include <cuda_bf16.h>
#include <cstdint>

// ============================ problem constants ============================
#define HDIM 256
#define SDIM 512
#define BDIM 2048
#define CDIM 10
#define BT   16
#define NCTA (BDIM / BT)        // 128
#define NTHR 256                // 8 warps, m=32 each; A=warps 0-3, B=4-7

// ============================ SMEM layout (bytes) ==========================
// W_lo (ALL 16 kk): [8 warps][2 mtiles][16 kk][32 lanes][16B] = 131072
#define WLO_OFF 0
#define WLO_SZ  131072
// h tiles, [k=256][n=16] bf16, 48B rows: buf0{hi,lo}, buf1{hi,lo}
#define HROW    48
#define HTILE   (HDIM * HROW)            // 12288
#define HB_OFF  WLO_SZ                   // 131072
#define HB_SZ   (4 * HTILE)              // 49152
#define XROW    516
#define XS_OFF  (HB_OFF + HB_SZ)         // 180224
#define XS_SZ   (BT * XROW * 4)          // 33024
#define SMEM_SZ (XS_OFF + XS_SZ)         // 213248

// ============================ device helpers ===============================
__device__ __forceinline__ uint32_t smem_u32(const void* p) {
    return (uint32_t)__cvta_generic_to_shared(p);
}

__device__ __forceinline__ void ldsm_x4_t(uint32_t* r, uint32_t addr) {
    asm volatile("ldmatrix.sync.aligned.m8n8.x4.trans.shared.b16 "
                 "{%0,%1,%2,%3}, [%4];"
                 : "=r"(r[0]), "=r"(r[1]), "=r"(r[2]), "=r"(r[3])
                 : "r"(addr));
}

__device__ __forceinline__ void mma16816(float* d, const uint32_t* a,
                                         uint32_t b0, uint32_t b1) {
    asm volatile("mma.sync.aligned.m16n8k16.row.col.f32.bf16.bf16.f32 "
                 "{%0,%1,%2,%3},{%4,%5,%6,%7},{%8,%9},{%0,%1,%2,%3};"
                 : "+f"(d[0]), "+f"(d[1]), "+f"(d[2]), "+f"(d[3])
                 : "r"(a[0]), "r"(a[1]), "r"(a[2]), "r"(a[3]),
                   "r"(b0), "r"(b1));
}

__device__ __forceinline__ uint32_t split2(float x, float y, uint32_t& lo) {
    uint32_t hi;
    asm("cvt.rn.bf16x2.f32 %0, %1, %2;" : "=r"(hi) : "f"(y), "f"(x));
    float fx = __uint_as_float(hi << 16);
    float fy = __uint_as_float(hi & 0xffff0000u);
    float rx = x - fx, ry = y - fy;
    asm("cvt.rn.bf16x2.f32 %0, %1, %2;" : "=r"(lo) : "f"(ry), "f"(rx));
    return hi;
}

// quad tanh: one rcp per four values (r12-validated)
__device__ __forceinline__ void tanh4(float* v) {
    const float C = 2.8853900817779268f;     // 2*log2(e)
    float u0 = fminf(v[0], 10.0f) * C;
    float u1 = fminf(v[1], 10.0f) * C;
    float u2 = fminf(v[2], 10.0f) * C;
    float u3 = fminf(v[3], 10.0f) * C;
    float d0 = exp2f(u0) + 1.0f;
    float d1 = exp2f(u1) + 1.0f;
    float d2 = exp2f(u2) + 1.0f;
    float d3 = exp2f(u3) + 1.0f;
    float m01 = d0 * d1, m23 = d2 * d3;
    float r;
    asm("rcp.approx.f32 %0, %1;" : "=f"(r) : "f"(m01 * m23));
    float r01 = r * m23, r23 = r * m01;
    v[0] = fmaf(r01 * d1, -2.0f, 1.0f);
    v[1] = fmaf(r01 * d0, -2.0f, 1.0f);
    v[2] = fmaf(r23 * d3, -2.0f, 1.0f);
    v[3] = fmaf(r23 * d2, -2.0f, 1.0f);
}

#define BAR_SYNC(id, cnt) \
    asm volatile("bar.sync %0, %1;" :: "r"(id), "r"(cnt) : "memory")
#define BAR_ARRIVE(id, cnt) \
    asm volatile("bar.arrive %0, %1;" :: "r"(id), "r"(cnt) : "memory")

// ---- one 8-kk GEMM block starting at compile-time KB (0 or 8) ----
#define BLOCK(KB)                                                            \
do {                                                                         \
    uint32_t bhv[2][4], blv[2][4];                                           \
    uint4 wav[2], wbv[2];                                                    \
    ldsm_x4_t(bhv[0], hhi + (uint32_t)(KB) * (16 * HROW));                   \
    ldsm_x4_t(blv[0], hlo + (uint32_t)(KB) * (16 * HROW));                   \
    wav[0] = *reinterpret_cast<const uint4*>(wloSA + (KB) * 512);            \
    wbv[0] = *reinterpret_cast<const uint4*>(wloSB + (KB) * 512);            \
    _Pragma("unroll")                                                        \
    for (int i = 0; i < 8; ++i) {                                            \
        const int cu = i & 1, nx = cu ^ 1;                                   \
        const int kk = (KB) + i;                                             \
        if (i < 7) {                                                         \
            ldsm_x4_t(bhv[nx], hhi + (uint32_t)(kk + 1) * (16 * HROW));      \
            ldsm_x4_t(blv[nx], hlo + (uint32_t)(kk + 1) * (16 * HROW));      \
            wav[nx] = *reinterpret_cast<const uint4*>(wloSA + (kk+1) * 512); \
            wbv[nx] = *reinterpret_cast<const uint4*>(wloSB + (kk+1) * 512); \
        }                                                                    \
        uint32_t wloA[4] = {wav[cu].x, wav[cu].y, wav[cu].z, wav[cu].w};     \
        uint32_t wloB[4] = {wbv[cu].x, wbv[cu].y, wbv[cu].z, wbv[cu].w};     \
        const uint32_t* aA  = whi + kk * 4;                                  \
        const uint32_t* aB  = whi + 64 + kk * 4;                             \
        const uint32_t* bh4 = bhv[cu];                                       \
        const uint32_t* bl4 = blv[cu];                                       \
        mma16816(DA0, aA,   bh4[0], bh4[1]);                                 \
        mma16816(DA0, aA,   bl4[0], bl4[1]);                                 \
        mma16816(DA0, wloA, bh4[0], bh4[1]);                                 \
        mma16816(DA1, aA,   bh4[2], bh4[3]);                                 \
        mma16816(DA1, aA,   bl4[2], bl4[3]);                                 \
        mma16816(DA1, wloA, bh4[2], bh4[3]);                                 \
        mma16816(DB0, aB,   bh4[0], bh4[1]);                                 \
        mma16816(DB0, aB,   bl4[0], bl4[1]);                                 \
        mma16816(DB0, wloB, bh4[0], bh4[1]);                                 \
        mma16816(DB1, aB,   bh4[2], bh4[3]);                                 \
        mma16816(DB1, aB,   bl4[2], bl4[3]);                                 \
        mma16816(DB1, wloB, bh4[2], bh4[3]);                                 \
    }                                                                        \
} while (0)

// ============================ kernel =======================================
extern "C" __global__ void __launch_bounds__(NTHR, 1)
rnn_anti_kernel(const float* __restrict__ x,
                const float* __restrict__ W_hx,
                const float* __restrict__ W_hh,
                const float* __restrict__ W_ph,
                const float* __restrict__ b_h,
                const float* __restrict__ b_p,
                float* __restrict__ out)
{
    extern __shared__ char sm[];
    const uint32_t smu = smem_u32(sm);

    const int tid  = threadIdx.x;
    const int w    = tid >> 5;          // warps 0-3: rows 0-127 (A); 4-7: high (B)
    const int lane = tid & 31;
    const int g    = lane >> 2;
    const int tIG  = lane & 3;
    const int m0   = w * 32;
    const int c0   = blockIdx.x * BT;
    const bool isA = (w < 4);

    // ---- stage x ----
    {
        float* xsw = (float*)(sm + XS_OFF);
        #pragma unroll 1
        for (int idx = tid; idx < BT * SDIM / 4; idx += NTHR) {
            int n = idx >> 7, t4 = idx & 127;
            float4 v = *reinterpret_cast<const float4*>(
                x + (size_t)(c0 + n) * SDIM + t4 * 4);
            *reinterpret_cast<float4*>(xsw + n * XROW + t4 * 4) = v;
        }
    }
    // ---- zero h buffer 0 (h(0)) ----
    {
        uint4 z = {0u, 0u, 0u, 0u};
        #pragma unroll 1
        for (int idx = tid; idx < 2 * HTILE / 16; idx += NTHR)
            *reinterpret_cast<uint4*>(sm + HB_OFF + idx * 16) = z;
    }

    // ---- gather W_hh fragments: hi -> regs; lo (all 16 kk) -> SMEM ----
    uint32_t whi[128];                   // [mtile][kk][4]
    {
        #pragma unroll
        for (int tl = 0; tl < 2; ++tl) {
            const int rA = m0 + tl * 16 + g;
            const int rB = rA + 8;
            const float* Wr0 = W_hh + (size_t)rA * HDIM;
            const float* Wr1 = W_hh + (size_t)rB * HDIM;
            char* wlo_base = sm + WLO_OFF +
                ((size_t)(w * 2 + tl) * 16) * 512 + (size_t)lane * 16;
            #pragma unroll
            for (int kk = 0; kk < 16; ++kk) {
                int cl = kk * 16 + 2 * tIG;
                int ch = cl + 8;
                float2 w00 = *reinterpret_cast<const float2*>(Wr0 + cl);
                float2 w10 = *reinterpret_cast<const float2*>(Wr1 + cl);
                float2 w01 = *reinterpret_cast<const float2*>(Wr0 + ch);
                float2 w11 = *reinterpret_cast<const float2*>(Wr1 + ch);
                uint4 lo;
                whi[tl * 64 + kk * 4 + 0] = split2(w00.x, w00.y, lo.x);
                whi[tl * 64 + kk * 4 + 1] = split2(w10.x, w10.y, lo.y);
                whi[tl * 64 + kk * 4 + 2] = split2(w01.x, w01.y, lo.z);
                whi[tl * 64 + kk * 4 + 3] = split2(w11.x, w11.y, lo.w);
                *reinterpret_cast<uint4*>(wlo_base + (size_t)kk * 512) = lo;
            }
        }
    }

    // epilogue constants
    const int rA0 = m0 + g, rA1 = rA0 + 8, rB0 = rA0 + 16, rB1 = rA0 + 24;
    const float wxA0 = W_hx[rA0], wxA1 = W_hx[rA1];
    const float wxB0 = W_hx[rB0], wxB1 = W_hx[rB1];
    const float bhA0 = b_h[rA0],  bhA1 = b_h[rA1];
    const float bhB0 = b_h[rB0],  bhB1 = b_h[rB1];

    const uint32_t lm_off = (uint32_t)((((lane >> 3) & 1) * 8 + (lane & 7)) * HROW
                                       + ((lane >> 4) * 16));
    const uint32_t hb_u32 = smu + HB_OFF;
    const char* wloSA = sm + WLO_OFF + ((size_t)(w * 2) * 16) * 512 + (size_t)lane * 16;
    const char* wloSB = wloSA + 16 * 512;
    const float* xs = (const float*)(sm + XS_OFF);
    const int cc = 2 * tIG;

    __syncthreads();

    // ---- antiphase seed: B-group delays ~1600 cyc ----
    if (!isA) {
        float z = (float)lane * 1.0e-8f;
        #pragma unroll 1
        for (int i = 0; i < 400; ++i)
            asm volatile("fma.rn.f32 %0, %0, 0f3F800001, 0f30000000;" : "+f"(z));
    }

    // ======================= time loop =======================
    #pragma unroll 1
    for (int t = 0; t < SDIM; ++t) {
        const uint32_t hhi = hb_u32 + (uint32_t)((t & 1) * 2 * HTILE) + lm_off;
        const uint32_t hlo = hhi + HTILE;

        const float x00 = xs[(cc + 0) * XROW + t];
        const float x01 = xs[(cc + 1) * XROW + t];
        const float x08 = xs[(cc + 8) * XROW + t];
        const float x09 = xs[(cc + 9) * XROW + t];

        float DA0[4] = { fmaf(wxA0, x00, bhA0), fmaf(wxA0, x01, bhA0),
                         fmaf(wxA1, x00, bhA1), fmaf(wxA1, x01, bhA1) };
        float DA1[4] = { fmaf(wxA0, x08, bhA0), fmaf(wxA0, x09, bhA0),
                         fmaf(wxA1, x08, bhA1), fmaf(wxA1, x09, bhA1) };
        float DB0[4] = { fmaf(wxB0, x00, bhB0), fmaf(wxB0, x01, bhB0),
                         fmaf(wxB1, x00, bhB1), fmaf(wxB1, x01, bhB1) };
        float DB1[4] = { fmaf(wxB0, x08, bhB0), fmaf(wxB0, x09, bhB0),
                         fmaf(wxB1, x08, bhB1), fmaf(wxB1, x09, bhB1) };

        if (isA) {
            BLOCK(0);                                    // own rows, gated bar1@t-1
            if (t > 0) BAR_SYNC((t & 1) ? 4 : 5, 256);   // B's h(t) high
            BLOCK(8);
        } else {
            BLOCK(8);                                    // own rows, gated bar3@t-1
            if (t > 0) BAR_SYNC((t & 1) ? 2 : 6, 256);   // A's h(t) low
            BLOCK(0);
        }

        // ---- epilogue: tanh4 + split + STS to buf (t+1)&1 ----
        tanh4(DA0); tanh4(DA1); tanh4(DB0); tanh4(DB1);

        char* ohi = sm + HB_OFF + ((t + 1) & 1) * 2 * HTILE;
        char* olo = ohi + HTILE;
        uint32_t hi, lo;

        hi = split2(DA0[0], DA0[1], lo);
        *reinterpret_cast<uint32_t*>(ohi + rA0 * HROW + 4 * tIG) = hi;
        *reinterpret_cast<uint32_t*>(olo + rA0 * HROW + 4 * tIG) = lo;
        hi = split2(DA0[2], DA0[3], lo);
        *reinterpret_cast<uint32_t*>(ohi + rA1 * HROW + 4 * tIG) = hi;
        *reinterpret_cast<uint32_t*>(olo + rA1 * HROW + 4 * tIG) = lo;
        hi = split2(DA1[0], DA1[1], lo);
        *reinterpret_cast<uint32_t*>(ohi + rA0 * HROW + 16 + 4 * tIG) = hi;
        *reinterpret_cast<uint32_t*>(olo + rA0 * HROW + 16 + 4 * tIG) = lo;
        hi = split2(DA1[2], DA1[3], lo);
        *reinterpret_cast<uint32_t*>(ohi + rA1 * HROW + 16 + 4 * tIG) = hi;
        *reinterpret_cast<uint32_t*>(olo + rA1 * HROW + 16 + 4 * tIG) = lo;
        hi = split2(DB0[0], DB0[1], lo);
        *reinterpret_cast<uint32_t*>(ohi + rB0 * HROW + 4 * tIG) = hi;
        *reinterpret_cast<uint32_t*>(olo + rB0 * HROW + 4 * tIG) = lo;
        hi = split2(DB0[2], DB0[3], lo);
        *reinterpret_cast<uint32_t*>(ohi + rB1 * HROW + 4 * tIG) = hi;
        *reinterpret_cast<uint32_t*>(olo + rB1 * HROW + 4 * tIG) = lo;
        hi = split2(DB1[0], DB1[1], lo);
        *reinterpret_cast<uint32_t*>(ohi + rB0 * HROW + 16 + 4 * tIG) = hi;
        *reinterpret_cast<uint32_t*>(olo + rB0 * HROW + 16 + 4 * tIG) = lo;
        hi = split2(DB1[2], DB1[3], lo);
        *reinterpret_cast<uint32_t*>(ohi + rB1 * HROW + 16 + 4 * tIG) = hi;
        *reinterpret_cast<uint32_t*>(olo + rB1 * HROW + 16 + 4 * tIG) = lo;

        // ---- publish + intra-group sync ----
        if (isA) {
            BAR_ARRIVE((t & 1) ? 6 : 2, 256);   // h(t+1) low -> B
            BAR_SYNC(1, 128);                   // A-internal
        } else {
            BAR_ARRIVE((t & 1) ? 5 : 4, 256);   // h(t+1) high -> A
            BAR_SYNC(3, 128);                   // B-internal
        }
    }

    __syncthreads();

    // ======================= final projection =======================
    // h(512) is in buffer (512 & 1) = 0.
    if (tid < BT * CDIM) {
        const int b = tid / CDIM, c = tid % CDIM;
        const char* hb = sm + HB_OFF;
        const char* lb = hb + HTILE;
        float s = b_p[c];
        #pragma unroll 4
        for (int i = 0; i < HDIM; ++i) {
            float h = __bfloat162float(*reinterpret_cast<const __nv_bfloat16*>(
                          hb + i * HROW + 2 * b))
                    + __bfloat162float(*reinterpret_cast<const __nv_bfloat16*>(
                          lb + i * HROW + 2 * b));
            s += W_ph[c * HDIM + i] * h;
        }
        out[(size_t)(c0 + b) * CDIM + c] = s;
    }
}

extern "C" void kernel_launch(void* const* d_in, const int* in_sizes, int n_in,
                              void* d_out, int out_size)
{
    const float* x    = (const float*)d_in[0];
    const float* W_hx = (const float*)d_in[1];
    const float* W_hh = (const float*)d_in[2];
    const float* W_ph = (const float*)d_in[3];
    const float* b_h  = (const float*)d_in[4];
    const float* b_p  = (const float*)d_in[5];
    float* out = (float*)d_out;

    cudaFuncSetAttribute(rnn_anti_kernel,
                         cudaFuncAttributeMaxDynamicSharedMemorySize, SMEM_SZ);
    rnn_anti_kernel<<<NCTA, NTHR, SMEM_SZ>>>(x, W_hx, W_hh, W_ph, b_h, b_p, out);
}